// round 14
// baseline (speedup 1.0000x reference)
#include <cuda_runtime.h>
#include <cuda_fp16.h>
#include <cstdint>

// ---------------- problem constants ----------------
#define BB    2
#define QN    1024
#define PAST  1024
#define MAXC  4096
#define HH    32
#define HKV   8
#define DD    128
#define HID   4096
#define KLEN  (PAST + QN)
#define NQKV  ((HH + 2*HKV) * DD)
#define GROUPS (HH / HKV)
#define SCALE 0.08838834764831845f
#define LOG2E 1.4426950408889634f

#define OUT_SZ1 (BB*QN*HID)
#define CACHE_SZ (BB*HKV*MAXC*DD)

// ---------------- scratch ----------------
__device__ __align__(16) float g_qkv  [BB*QN*NQKV];
__device__ __align__(16) float g_attnO[BB*HH*QN*DD];

__device__ __align__(16) __half gA_hi [BB*QN*HID];
__device__ __align__(16) __half gA_lo [BB*QN*HID];
__device__ __align__(16) __half gWq_h [NQKV*HID];
__device__ __align__(16) __half gWo_h [HID*HKV*DD];
__device__ __align__(16) __half gXo_hi[BB*QN*HKV*DD];
__device__ __align__(16) __half gXo_lo[BB*QN*HKV*DD];

__device__ __align__(16) __half gQ_hi [BB*HH*QN*DD];
__device__ __align__(16) __half gQ_lo [BB*HH*QN*DD];
__device__ __align__(16) __half gKc_h [BB*HKV*KLEN*DD];
__device__ __align__(16) __half gVc_h [BB*HKV*KLEN*DD];

// ================= PTX helpers =================
__device__ __forceinline__ uint32_t smem_u32(const void* p) {
    uint32_t a;
    asm("{ .reg .u64 t; cvta.to.shared.u64 t, %1; cvt.u32.u64 %0, t; }" : "=r"(a) : "l"(p));
    return a;
}
__device__ __forceinline__ void ldm_x4(uint32_t* r, uint32_t addr) {
    asm volatile("ldmatrix.sync.aligned.m8n8.x4.shared.b16 {%0,%1,%2,%3}, [%4];"
                 : "=r"(r[0]), "=r"(r[1]), "=r"(r[2]), "=r"(r[3]) : "r"(addr));
}
__device__ __forceinline__ void ldm_x4t(uint32_t* r, uint32_t addr) {
    asm volatile("ldmatrix.sync.aligned.m8n8.x4.trans.shared.b16 {%0,%1,%2,%3}, [%4];"
                 : "=r"(r[0]), "=r"(r[1]), "=r"(r[2]), "=r"(r[3]) : "r"(addr));
}
__device__ __forceinline__ void mma_f16(float* d, const uint32_t* a, const uint32_t* b) {
    asm volatile(
        "mma.sync.aligned.m16n8k16.row.col.f32.f16.f16.f32 "
        "{%0,%1,%2,%3}, {%4,%5,%6,%7}, {%8,%9}, {%0,%1,%2,%3};"
        : "+f"(d[0]), "+f"(d[1]), "+f"(d[2]), "+f"(d[3])
        : "r"(a[0]), "r"(a[1]), "r"(a[2]), "r"(a[3]), "r"(b[0]), "r"(b[1]));
}
__device__ __forceinline__ void cp16(uint32_t dst, const void* src) {
    asm volatile("cp.async.cg.shared.global [%0], [%1], 16;" :: "r"(dst), "l"(src));
}
__device__ __forceinline__ uint32_t pack_h2(float x, float y) {
    __half2 h = __floats2half2_rn(x, y);
    return *(uint32_t*)&h;
}
__device__ __forceinline__ float ex2(float x) {
    float y;
    asm("ex2.approx.f32 %0, %1;" : "=f"(y) : "f"(x));
    return y;
}

// ================= fused input prep =================
__global__ void prep_inputs(const float* __restrict__ hidden,
                            const float* __restrict__ kc, const float* __restrict__ vc,
                            float* __restrict__ out_k, float* __restrict__ out_v) {
    long i = (long)blockIdx.x * 256 + threadIdx.x;
    if (i >= (long)CACHE_SZ) return;
    float kx = kc[i], vx = vc[i];
    out_k[i] = kx;
    out_v[i] = vx;
    int d = (int)(i & (DD - 1));
    long t = i >> 7;
    int pos = (int)(t & (MAXC - 1));
    if (pos < PAST) {
        long tt = t >> 12;
        long dst = (tt * KLEN + pos) * DD + d;
        gKc_h[dst] = __float2half_rn(kx);
        gVc_h[dst] = __float2half_rn(vx);
    }
    float x = hidden[i];
    __half h = __float2half_rn(x);
    gA_hi[i] = h;
    gA_lo[i] = __float2half_rn(x - __half2float(h));
}

__global__ void conv_T_h(const float* __restrict__ src, __half* __restrict__ hi,
                         int K, int N) {
    __shared__ float t[32][33];
    int bn = blockIdx.x * 32, bk = blockIdx.y * 32;
    int x = threadIdx.x, y = threadIdx.y;
    #pragma unroll
    for (int i = 0; i < 32; i += 8)
        t[y + i][x] = src[(long)(bk + y + i) * N + bn + x];
    __syncthreads();
    #pragma unroll
    for (int i = 0; i < 32; i += 8)
        hi[(long)(bn + y + i) * K + bk + x] = __float2half_rn(t[x][y + i]);
}

// ================= warp-MMA fp16 2-term GEMM =================
#define TILE_B  8192
#define STAGE_B (3 * TILE_B)
#define NST     4
#define GEMM_SMEM (NST * STAGE_B)

__device__ __forceinline__ uint32_t swz(int row, int ch) {
    return (uint32_t)(row * 64 + ((ch ^ ((row >> 1) & 3)) << 4));
}

__device__ __forceinline__ void fill_stage(
    uint32_t sb, int kt, int m0, int n0, int K,
    const __half* Ahi, const __half* Alo, const __half* Bh, int tid)
{
    long k0 = (long)kt * 32;
    const __half* bases[3] = {Ahi, Alo, Bh};
    #pragma unroll
    for (int t = 0; t < 3; t++) {
        const __half* bp = bases[t];
        int r0 = (t < 2) ? m0 : n0;
        #pragma unroll
        for (int i = 0; i < 4; i++) {
            int idx = tid + i * 128;
            int row = idx >> 2, ch = idx & 3;
            cp16(sb + t * TILE_B + swz(row, ch), bp + (long)(r0 + row) * K + k0 + ch * 8);
        }
    }
}

__global__ void __launch_bounds__(128, 2) gemm_mma(
    const __half* __restrict__ Ahi, const __half* __restrict__ Alo,
    const __half* __restrict__ Bh,
    float* __restrict__ C, int M, int N, int K)
{
    extern __shared__ char smraw[];
    uint32_t s0 = smem_u32(smraw);
    int tid = threadIdx.x, lane = tid & 31, wid = tid >> 5;
    int wm = wid & 1, wn = wid >> 1;
    int m0 = blockIdx.y * 128, n0 = blockIdx.x * 128;

    float acc[4][8][4];
    #pragma unroll
    for (int i = 0; i < 4; i++)
        #pragma unroll
        for (int j = 0; j < 8; j++)
            #pragma unroll
            for (int k = 0; k < 4; k++) acc[i][j][k] = 0.f;

    int nk = K >> 5;
    #pragma unroll
    for (int p = 0; p < 4; p++) {
        fill_stage(s0 + p * STAGE_B, p, m0, n0, K, Ahi, Alo, Bh, tid);
        asm volatile("cp.async.commit_group;" ::: "memory");
    }

    int a_row = wm * 64 + (lane & 15);
    int a_cb  = lane >> 4;
    int b_row = wn * 64 + (lane & 7) + (lane >> 4) * 8;
    int b_cb  = (lane >> 3) & 1;

    for (int kt = 0; kt < nk; kt += 2) {
        asm volatile("cp.async.wait_group 2;" ::: "memory");
        __syncthreads();

        if (kt + 2 < nk) {
            fill_stage(s0 + ((kt + 2) & 3) * STAGE_B, kt + 2, m0, n0, K, Ahi, Alo, Bh, tid);
            asm volatile("cp.async.commit_group;" ::: "memory");
        }
        if (kt + 3 < nk) {
            fill_stage(s0 + ((kt + 3) & 3) * STAGE_B, kt + 3, m0, n0, K, Ahi, Alo, Bh, tid);
            asm volatile("cp.async.commit_group;" ::: "memory");
        }

        #pragma unroll
        for (int half = 0; half < 2; half++) {
            uint32_t sb = s0 + ((kt + half) & 3) * STAGE_B;
            uint32_t sbB = sb + 2 * TILE_B;

            uint32_t a[2][4][4];
            uint32_t bfr[2][4];
            #pragma unroll
            for (int hl = 0; hl < 2; hl++)
                #pragma unroll
                for (int mt = 0; mt < 4; mt++)
                    ldm_x4(a[hl][mt], sb + hl * TILE_B + swz(a_row + mt * 16, a_cb));
            ldm_x4(bfr[0], sbB + swz(b_row, b_cb));

            #pragma unroll
            for (int idx = 0; idx < 8; idx++) {
                int buf = idx & 1;
                if (idx < 7) {
                    int nks = (idx + 1) >> 2, nnp = (idx + 1) & 3;
                    ldm_x4(bfr[buf ^ 1], sbB + swz(b_row + nnp * 16, nks * 2 + b_cb));
                }
                int np = idx & 3;
                uint32_t* bh = bfr[buf];
                // hi pass: 8 distinct accumulators
                #pragma unroll
                for (int mt = 0; mt < 4; mt++)
                    #pragma unroll
                    for (int nt = 0; nt < 2; nt++)
                        mma_f16(acc[mt][np * 2 + nt], a[0][mt], &bh[nt * 2]);
                // lo pass: same accs, 8 MMAs apart
                #pragma unroll
                for (int mt = 0; mt < 4; mt++)
                    #pragma unroll
                    for (int nt = 0; nt < 2; nt++)
                        mma_f16(acc[mt][np * 2 + nt], a[1][mt], &bh[nt * 2]);
                if (idx == 3) {
                    #pragma unroll
                    for (int hl = 0; hl < 2; hl++)
                        #pragma unroll
                        for (int mt = 0; mt < 4; mt++)
                            ldm_x4(a[hl][mt], sb + hl * TILE_B + swz(a_row + mt * 16, 2 + a_cb));
                }
            }
        }
    }

    int row0 = m0 + wm * 64 + (lane >> 2);
    int col0 = n0 + wn * 64 + (lane & 3) * 2;
    #pragma unroll
    for (int mt = 0; mt < 4; mt++)
        #pragma unroll
        for (int nt = 0; nt < 8; nt++) {
            float* d = acc[mt][nt];
            long r = row0 + mt * 16;
            long c = col0 + nt * 8;
            *(float2*)(C + r * N + c)       = make_float2(d[0], d[1]);
            *(float2*)(C + (r + 8) * N + c) = make_float2(d[2], d[3]);
        }
}

// ---------------- RMSNorm + RoPE + scatter + fp16 emission ----------------
__global__ void qkv_post_kernel(const float* __restrict__ rope,
                                const int*   __restrict__ start,
                                const float* __restrict__ qw,
                                const float* __restrict__ kw,
                                float* __restrict__ out_k,
                                float* __restrict__ out_v)
{
    int sub  = threadIdx.x >> 7;
    int tid  = threadIdx.x & 127;
    int slot = blockIdx.x * 4 + sub;
    int q    = blockIdx.y;
    int b    = blockIdx.z;
    long row = ((long)b * QN + q) * NQKV;
    float x = g_qkv[row + (long)slot * DD + tid];
    int pos = start[b] + q;

    if (slot >= 40) {
        int h = slot - 40;
        out_v[(((long)b * HKV + h) * MAXC + pos) * DD + tid] = x;
        gVc_h[(((long)b * HKV + h) * KLEN + pos) * DD + tid] = __float2half_rn(x);
        return;
    }

    __shared__ float red[4][4];
    __shared__ float sm[4][DD];
    float v2 = x * x;
    #pragma unroll
    for (int m = 16; m; m >>= 1) v2 += __shfl_xor_sync(0xffffffffu, v2, m);
    if ((tid & 31) == 0) red[sub][tid >> 5] = v2;
    __syncthreads();
    float tot = red[sub][0] + red[sub][1] + red[sub][2] + red[sub][3];
    float scl = rsqrtf(tot * (1.f / DD) + 1e-6f);
    const float* w = (slot < 32) ? qw : kw;
    sm[sub][tid] = x * scl * w[tid];
    __syncthreads();

    int i = (tid < 64) ? tid : tid - 64;
    float c = rope[(long)pos * DD + i];
    float s = rope[(long)pos * DD + 64 + i];
    float x1 = sm[sub][i], x2 = sm[sub][i + 64];
    float o = (tid < 64) ? (x1 * c - x2 * s) : (x2 * c + x1 * s);

    if (slot < 32) {
        float xs = o * (SCALE * LOG2E);
        long qi = (((long)b * HH + slot) * QN + q) * DD + tid;
        __half qh = __float2half_rn(xs);
        gQ_hi[qi] = qh;
        gQ_lo[qi] = __float2half_rn(xs - __half2float(qh));
    } else {
        int h = slot - 32;
        out_k[(((long)b * HKV + h) * MAXC + pos) * DD + tid] = o;
        gKc_h[(((long)b * HKV + h) * KLEN + pos) * DD + tid] = __float2half_rn(o);
    }
}

// ================= flash attention =================
#define APITCHB 272
#define AQ 64
#define ATILE (AQ * APITCHB)
#define ATTN_SMEM (6 * ATILE)

__device__ __forceinline__ void load_tile_h(uint32_t dst,
    const __half* src, long rowbase, int tid)
{
    #pragma unroll
    for (int i = 0; i < 8; i++) {
        int idx = tid + i * 128;
        int row = idx >> 4, ch = idx & 15;
        cp16(dst + row * APITCHB + ch * 16, src + rowbase + (long)row * DD + (ch << 3));
    }
}

__global__ void __launch_bounds__(128, 2) attn_mma()
{
    extern __shared__ char smraw[];
    uint32_t T0 = smem_u32(smraw);
    int tid = threadIdx.x, lane = tid & 31, w = tid >> 5;
    int qt = gridDim.x - 1 - blockIdx.x;
    int h = blockIdx.y, b = blockIdx.z;
    int kvh = h >> 2;
    int q0 = qt * 64;

    long qbase  = ((long)(b * HH + h) * QN + q0) * DD;
    long kvbase = (long)(b * HKV + kvh) * KLEN * DD;

    const int a_row  = w * 16 + (lane & 15);
    const int a_kb   = (lane >> 4) * 16;
    const int b_row  = (lane & 7) + (lane >> 4) * 8;
    const int b_kb   = ((lane >> 3) & 1) * 16;
    const int v_row  = lane & 15;
    const int v_col  = (lane >> 4) * 8;

    load_tile_h(T0 + 4 * ATILE, gQ_hi, qbase, tid);
    load_tile_h(T0 + 5 * ATILE, gQ_lo, qbase, tid);
    load_tile_h(T0,             gKc_h, kvbase, tid);
    load_tile_h(T0 + ATILE,     gVc_h, kvbase, tid);
    asm volatile("cp.async.commit_group;" ::: "memory");
    load_tile_h(T0 + 2 * ATILE, gKc_h, kvbase + 64 * DD, tid);
    load_tile_h(T0 + 3 * ATILE, gVc_h, kvbase + 64 * DD, tid);
    asm volatile("cp.async.commit_group;" ::: "memory");

    asm volatile("cp.async.wait_group 1;" ::: "memory");
    __syncthreads();

    uint32_t qfr[8][2][4];
    #pragma unroll
    for (int ks = 0; ks < 8; ks++) {
        uint32_t qa = T0 + 4 * ATILE + a_row * APITCHB + ks * 32 + a_kb;
        ldm_x4(qfr[ks][0], qa);
        ldm_x4(qfr[ks][1], qa + ATILE);
    }

    const int nc = 17 + qt;

    float O[16][4];
    #pragma unroll
    for (int i = 0; i < 16; i++)
        #pragma unroll
        for (int j = 0; j < 4; j++) O[i][j] = 0.f;
    float m0 = -1e30f, m1 = -1e30f, l0 = 0.f, l1 = 0.f;

    for (int c = 0; c < nc; c++) {
        int st = c % 3;
        uint32_t sK = T0 + 2 * st * ATILE;
        uint32_t sV = sK + ATILE;

        asm volatile("cp.async.wait_group 1;" ::: "memory");
        __syncthreads();

        if (c + 2 < nc) {
            int rs = (c + 2) % 3;
            long nb = kvbase + (long)(c + 2) * 64 * DD;
            load_tile_h(T0 + 2 * rs * ATILE,       gKc_h, nb, tid);
            load_tile_h(T0 + (2 * rs + 1) * ATILE, gVc_h, nb, tid);
        }
        asm volatile("cp.async.commit_group;" ::: "memory");

        // ---- S = Q K^T (hi pass then lo pass over 8 distinct accs) ----
        float S[8][4];
        #pragma unroll
        for (int j = 0; j < 8; j++)
            #pragma unroll
            for (int k = 0; k < 4; k++) S[j][k] = 0.f;

        #pragma unroll
        for (int ks = 0; ks < 8; ks++) {
            uint32_t kf[4][4];
            #pragma unroll
            for (int np = 0; np < 4; np++)
                ldm_x4(kf[np], sK + (np * 16 + b_row) * APITCHB + ks * 32 + b_kb);
            #pragma unroll
            for (int np = 0; np < 4; np++)
                #pragma unroll
                for (int nt = 0; nt < 2; nt++)
                    mma_f16(S[np * 2 + nt], qfr[ks][0], &kf[np][nt * 2]);
            #pragma unroll
            for (int np = 0; np < 4; np++)
                #pragma unroll
                for (int nt = 0; nt < 2; nt++)
                    mma_f16(S[np * 2 + nt], qfr[ks][1], &kf[np][nt * 2]);
        }

        if (c == nc - 1) {
            int klim0 = PAST + q0 + w * 16 + (lane >> 2);
            int klim1 = klim0 + 8;
            int kb = c * 64;
            #pragma unroll
            for (int j = 0; j < 8; j++) {
                int col = kb + j * 8 + (lane & 3) * 2;
                if (col > klim0)     S[j][0] = -1e30f;
                if (col + 1 > klim0) S[j][1] = -1e30f;
                if (col > klim1)     S[j][2] = -1e30f;
                if (col + 1 > klim1) S[j][3] = -1e30f;
            }
        }

        // ---- online softmax (base-2) ----
        float mx0 = -1e30f, mx1 = -1e30f;
        #pragma unroll
        for (int j = 0; j < 8; j++) {
            mx0 = fmaxf(mx0, fmaxf(S[j][0], S[j][1]));
            mx1 = fmaxf(mx1, fmaxf(S[j][2], S[j][3]));
        }
        mx0 = fmaxf(mx0, __shfl_xor_sync(0xffffffffu, mx0, 1));
        mx0 = fmaxf(mx0, __shfl_xor_sync(0xffffffffu, mx0, 2));
        mx1 = fmaxf(mx1, __shfl_xor_sync(0xffffffffu, mx1, 1));
        mx1 = fmaxf(mx1, __shfl_xor_sync(0xffffffffu, mx1, 2));
        float mn0 = fmaxf(m0, mx0), mn1 = fmaxf(m1, mx1);
        float al0 = ex2(m0 - mn0), al1 = ex2(m1 - mn1);
        float r0 = 0.f, r1 = 0.f;
        #pragma unroll
        for (int j = 0; j < 8; j++) {
            S[j][0] = ex2(S[j][0] - mn0);
            S[j][1] = ex2(S[j][1] - mn0);
            S[j][2] = ex2(S[j][2] - mn1);
            S[j][3] = ex2(S[j][3] - mn1);
            r0 += S[j][0] + S[j][1];
            r1 += S[j][2] + S[j][3];
        }
        r0 += __shfl_xor_sync(0xffffffffu, r0, 1);
        r0 += __shfl_xor_sync(0xffffffffu, r0, 2);
        r1 += __shfl_xor_sync(0xffffffffu, r1, 1);
        r1 += __shfl_xor_sync(0xffffffffu, r1, 2);
        l0 = l0 * al0 + r0;
        l1 = l1 * al1 + r1;
        m0 = mn0; m1 = mn1;
        #pragma unroll
        for (int i = 0; i < 16; i++) {
            O[i][0] *= al0; O[i][1] *= al0;
            O[i][2] *= al1; O[i][3] *= al1;
        }

        // ---- P -> fp16 hi/lo A-frags ----
        uint32_t pa_h[4][4], pa_l[4][4];
        #pragma unroll
        for (int kt = 0; kt < 4; kt++) {
            int j0 = 2 * kt, j1 = 2 * kt + 1;
            float v00 = S[j0][0], v01 = S[j0][1], v02 = S[j0][2], v03 = S[j0][3];
            float v10 = S[j1][0], v11 = S[j1][1], v12 = S[j1][2], v13 = S[j1][3];
            pa_h[kt][0] = pack_h2(v00, v01);
            pa_h[kt][1] = pack_h2(v02, v03);
            pa_h[kt][2] = pack_h2(v10, v11);
            pa_h[kt][3] = pack_h2(v12, v13);
            __half2* hp;
            hp = (__half2*)&pa_h[kt][0];
            pa_l[kt][0] = pack_h2(v00 - __half2float(hp->x), v01 - __half2float(hp->y));
            hp = (__half2*)&pa_h[kt][1];
            pa_l[kt][1] = pack_h2(v02 - __half2float(hp->x), v03 - __half2float(hp->y));
            hp = (__half2*)&pa_h[kt][2];
            pa_l[kt][2] = pack_h2(v10 - __half2float(hp->x), v11 - __half2float(hp->y));
            hp = (__half2*)&pa_h[kt][3];
            pa_l[kt][3] = pack_h2(v12 - __half2float(hp->x), v13 - __half2float(hp->y));
        }

        // ---- O += P V (np pairs, hi pass then lo pass) ----
        #pragma unroll
        for (int kt = 0; kt < 4; kt++) {
            #pragma unroll
            for (int npp = 0; npp < 4; npp++) {
                int np0 = npp * 2, np1 = npp * 2 + 1;
                uint32_t vf0[4], vf1[4];
                ldm_x4t(vf0, sV + (kt * 16 + v_row) * APITCHB + (np0 * 16 + v_col) * 2);
                ldm_x4t(vf1, sV + (kt * 16 + v_row) * APITCHB + (np1 * 16 + v_col) * 2);
                // hi pass: 4 distinct accs
                mma_f16(O[np0 * 2 + 0], pa_h[kt], &vf0[0]);
                mma_f16(O[np0 * 2 + 1], pa_h[kt], &vf0[2]);
                mma_f16(O[np1 * 2 + 0], pa_h[kt], &vf1[0]);
                mma_f16(O[np1 * 2 + 1], pa_h[kt], &vf1[2]);
                // lo pass
                mma_f16(O[np0 * 2 + 0], pa_l[kt], &vf0[0]);
                mma_f16(O[np0 * 2 + 1], pa_l[kt], &vf0[2]);
                mma_f16(O[np1 * 2 + 0], pa_l[kt], &vf1[0]);
                mma_f16(O[np1 * 2 + 1], pa_l[kt], &vf1[2]);
            }
        }
    }

    float inv0 = 1.f / l0, inv1 = 1.f / l1;
    int row0 = q0 + w * 16 + (lane >> 2);
    float* ob = g_attnO + ((long)(b * HH + h) * QN) * DD;
    #pragma unroll
    for (int np = 0; np < 16; np++) {
        int col = np * 8 + (lane & 3) * 2;
        *(float2*)(ob + (long)row0 * DD + col)       = make_float2(O[np][0] * inv0, O[np][1] * inv0);
        *(float2*)(ob + (long)(row0 + 8) * DD + col) = make_float2(O[np][2] * inv1, O[np][3] * inv1);
    }
}

// ---------------- group sum + fp16 hi/lo ----------------
__global__ void group_sum_kernel()
{
    long i = (long)blockIdx.x * 256 + threadIdx.x;
    if (i >= (long)BB * QN * HKV * DD) return;
    int d = (int)(i & (DD - 1));
    long t = i >> 7;
    int kvh = (int)(t & (HKV - 1));
    t >>= 3;
    int q = (int)(t % QN);
    int b = (int)(t / QN);
    float sum = 0.f;
    #pragma unroll
    for (int g = 0; g < GROUPS; g++)
        sum += g_attnO[(((long)b * HH + kvh * GROUPS + g) * QN + q) * DD + d];
    __half h = __float2half_rn(sum);
    gXo_hi[i] = h;
    gXo_lo[i] = __float2half_rn(sum - __half2float(h));
}

// ---------------- launch ----------------
static __half* sym_addr_h(const void* sym) {
    void* p = nullptr;
    cudaGetSymbolAddress(&p, sym);
    return (__half*)p;
}
static float* sym_addr_f(const void* sym) {
    void* p = nullptr;
    cudaGetSymbolAddress(&p, sym);
    return (float*)p;
}

extern "C" void kernel_launch(void* const* d_in, const int* in_sizes, int n_in,
                              void* d_out, int out_size)
{
    const float* hidden = (const float*)d_in[0];
    const float* kcache = (const float*)d_in[1];
    const float* vcache = (const float*)d_in[2];
    const float* rope   = (const float*)d_in[3];
    const int*   start  = (const int*)  d_in[5];
    const float* w_qkv  = (const float*)d_in[6];
    const float* w_o    = (const float*)d_in[7];
    const float* qw     = (const float*)d_in[8];
    const float* kw     = (const float*)d_in[9];

    float* out      = (float*)d_out;
    float* out_attn = out;
    float* out_k    = out + OUT_SZ1;
    float* out_v    = out + OUT_SZ1 + CACHE_SZ;

    float* s_qkv = sym_addr_f(g_qkv);
    __half* sA_hi = sym_addr_h(gA_hi);  __half* sA_lo = sym_addr_h(gA_lo);
    __half* sWq_h = sym_addr_h(gWq_h);  __half* sWo_h = sym_addr_h(gWo_h);
    __half* sXo_hi = sym_addr_h(gXo_hi); __half* sXo_lo = sym_addr_h(gXo_lo);

    cudaFuncSetAttribute(gemm_mma, cudaFuncAttributeMaxDynamicSharedMemorySize, GEMM_SMEM);
    cudaFuncSetAttribute(attn_mma, cudaFuncAttributeMaxDynamicSharedMemorySize, ATTN_SMEM);

    // 1. fused prep
    prep_inputs<<<(CACHE_SZ + 255) / 256, 256>>>(hidden, kcache, vcache, out_k, out_v);

    // 2. weight conversions
    conv_T_h<<<dim3(NQKV / 32, HID / 32), dim3(32, 8)>>>(w_qkv, sWq_h, HID, NQKV);
    conv_T_h<<<dim3(HID / 32, (HKV*DD) / 32), dim3(32, 8)>>>(w_o, sWo_h, HKV*DD, HID);

    // 3. QKV projection
    gemm_mma<<<dim3(NQKV / 128, (BB*QN) / 128), 128, GEMM_SMEM>>>(
        sA_hi, sA_lo, sWq_h, s_qkv, BB*QN, NQKV, HID);

    // 4. RMSNorm + RoPE + scatter + fp16 emission
    qkv_post_kernel<<<dim3(12, QN, BB), 512>>>(rope, start, qw, kw, out_k, out_v);

    // 5. flash attention
    attn_mma<<<dim3(QN / 64, HH, BB), 128, ATTN_SMEM>>>();

    // 6. group-sum + fp16 hi/lo
    group_sum_kernel<<<(BB*QN*HKV*DD + 255) / 256, 256>>>();

    // 7. output projection
    gemm_mma<<<dim3(HID / 128, (BB*QN) / 128), 128, GEMM_SMEM>>>(
        sXo_hi, sXo_lo, sWo_h, out_attn, BB*QN, HID, HKV*DD);
}

// round 15
// speedup vs baseline: 1.0406x; 1.0406x over previous
#include <cuda_runtime.h>
#include <cuda_fp16.h>
#include <cstdint>

// ---------------- problem constants ----------------
#define BB    2
#define QN    1024
#define PAST  1024
#define MAXC  4096
#define HH    32
#define HKV   8
#define DD    128
#define HID   4096
#define KLEN  (PAST + QN)
#define NQKV  ((HH + 2*HKV) * DD)
#define GROUPS (HH / HKV)
#define SCALE 0.08838834764831845f
#define LOG2E 1.4426950408889634f

#define OUT_SZ1 (BB*QN*HID)
#define CACHE_SZ (BB*HKV*MAXC*DD)

// ---------------- scratch ----------------
__device__ __align__(16) float g_attnO[BB*HH*QN*DD];

__device__ __align__(16) __half gA_hi [BB*QN*HID];
__device__ __align__(16) __half gA_lo [BB*QN*HID];
__device__ __align__(16) __half gWq_h [NQKV*HID];
__device__ __align__(16) __half gWo_h [HID*HKV*DD];
__device__ __align__(16) __half gXo_hi[BB*QN*HKV*DD];
__device__ __align__(16) __half gXo_lo[BB*QN*HKV*DD];

__device__ __align__(16) __half gQ_hi [BB*HH*QN*DD];
__device__ __align__(16) __half gQ_lo [BB*HH*QN*DD];
__device__ __align__(16) __half gKc_h [BB*HKV*KLEN*DD];
__device__ __align__(16) __half gVc_h [BB*HKV*KLEN*DD];

// ================= PTX helpers =================
__device__ __forceinline__ uint32_t smem_u32(const void* p) {
    uint32_t a;
    asm("{ .reg .u64 t; cvta.to.shared.u64 t, %1; cvt.u32.u64 %0, t; }" : "=r"(a) : "l"(p));
    return a;
}
__device__ __forceinline__ void ldm_x4(uint32_t* r, uint32_t addr) {
    asm volatile("ldmatrix.sync.aligned.m8n8.x4.shared.b16 {%0,%1,%2,%3}, [%4];"
                 : "=r"(r[0]), "=r"(r[1]), "=r"(r[2]), "=r"(r[3]) : "r"(addr));
}
__device__ __forceinline__ void ldm_x4t(uint32_t* r, uint32_t addr) {
    asm volatile("ldmatrix.sync.aligned.m8n8.x4.trans.shared.b16 {%0,%1,%2,%3}, [%4];"
                 : "=r"(r[0]), "=r"(r[1]), "=r"(r[2]), "=r"(r[3]) : "r"(addr));
}
__device__ __forceinline__ void mma_f16(float* d, const uint32_t* a, const uint32_t* b) {
    asm volatile(
        "mma.sync.aligned.m16n8k16.row.col.f32.f16.f16.f32 "
        "{%0,%1,%2,%3}, {%4,%5,%6,%7}, {%8,%9}, {%0,%1,%2,%3};"
        : "+f"(d[0]), "+f"(d[1]), "+f"(d[2]), "+f"(d[3])
        : "r"(a[0]), "r"(a[1]), "r"(a[2]), "r"(a[3]), "r"(b[0]), "r"(b[1]));
}
__device__ __forceinline__ void cp16(uint32_t dst, const void* src) {
    asm volatile("cp.async.cg.shared.global [%0], [%1], 16;" :: "r"(dst), "l"(src));
}
__device__ __forceinline__ uint32_t pack_h2(float x, float y) {
    __half2 h = __floats2half2_rn(x, y);
    return *(uint32_t*)&h;
}
__device__ __forceinline__ float ex2(float x) {
    float y;
    asm("ex2.approx.f32 %0, %1;" : "=f"(y) : "f"(x));
    return y;
}

// ================= fused input prep =================
__global__ void prep_inputs(const float* __restrict__ hidden,
                            const float* __restrict__ kc, const float* __restrict__ vc,
                            float* __restrict__ out_k, float* __restrict__ out_v) {
    long i = (long)blockIdx.x * 256 + threadIdx.x;
    if (i >= (long)CACHE_SZ) return;
    float kx = kc[i], vx = vc[i];
    out_k[i] = kx;
    out_v[i] = vx;
    int d = (int)(i & (DD - 1));
    long t = i >> 7;
    int pos = (int)(t & (MAXC - 1));
    if (pos < PAST) {
        long tt = t >> 12;
        long dst = (tt * KLEN + pos) * DD + d;
        gKc_h[dst] = __float2half_rn(kx);
        gVc_h[dst] = __float2half_rn(vx);
    }
    float x = hidden[i];
    __half h = __float2half_rn(x);
    gA_hi[i] = h;
    gA_lo[i] = __float2half_rn(x - __half2float(h));
}

__global__ void conv_T_h(const float* __restrict__ src, __half* __restrict__ hi,
                         int K, int N) {
    __shared__ float t[32][33];
    int bn = blockIdx.x * 32, bk = blockIdx.y * 32;
    int x = threadIdx.x, y = threadIdx.y;
    #pragma unroll
    for (int i = 0; i < 32; i += 8)
        t[y + i][x] = src[(long)(bk + y + i) * N + bn + x];
    __syncthreads();
    #pragma unroll
    for (int i = 0; i < 32; i += 8)
        hi[(long)(bn + y + i) * K + bk + x] = __float2half_rn(t[x][y + i]);
}

// ================= warp-MMA fp16 2-term GEMM =================
#define TILE_B  8192
#define STAGE_B (3 * TILE_B)
#define NST     4
#define GEMM_SMEM (NST * STAGE_B)          // 98304 (>= 128*129*4 = 66048 for fused epilogue)

__device__ __forceinline__ uint32_t swz(int row, int ch) {
    return (uint32_t)(row * 64 + ((ch ^ ((row >> 1) & 3)) << 4));
}

__device__ __forceinline__ void fill_stage(
    uint32_t sb, int kt, int m0, int n0, int K,
    const __half* Ahi, const __half* Alo, const __half* Bh, int tid)
{
    long k0 = (long)kt * 32;
    const __half* bases[3] = {Ahi, Alo, Bh};
    #pragma unroll
    for (int t = 0; t < 3; t++) {
        const __half* bp = bases[t];
        int r0 = (t < 2) ? m0 : n0;
        #pragma unroll
        for (int i = 0; i < 4; i++) {
            int idx = tid + i * 128;
            int row = idx >> 2, ch = idx & 3;
            cp16(sb + t * TILE_B + swz(row, ch), bp + (long)(r0 + row) * K + k0 + ch * 8);
        }
    }
}

template<bool FUSED>
__global__ void __launch_bounds__(128, 2) gemm_mma(
    const __half* __restrict__ Ahi, const __half* __restrict__ Alo,
    const __half* __restrict__ Bh,
    float* __restrict__ C, int M, int N, int K,
    const float* __restrict__ rope, const int* __restrict__ start,
    const float* __restrict__ qw, const float* __restrict__ kw,
    float* __restrict__ out_k, float* __restrict__ out_v)
{
    extern __shared__ char smraw[];
    uint32_t s0 = smem_u32(smraw);
    int tid = threadIdx.x, lane = tid & 31, wid = tid >> 5;
    int wm = wid & 1, wn = wid >> 1;
    int m0 = blockIdx.y * 128, n0 = blockIdx.x * 128;

    float acc[4][8][4];
    #pragma unroll
    for (int i = 0; i < 4; i++)
        #pragma unroll
        for (int j = 0; j < 8; j++)
            #pragma unroll
            for (int k = 0; k < 4; k++) acc[i][j][k] = 0.f;

    int nk = K >> 5;
    #pragma unroll
    for (int p = 0; p < 4; p++) {
        fill_stage(s0 + p * STAGE_B, p, m0, n0, K, Ahi, Alo, Bh, tid);
        asm volatile("cp.async.commit_group;" ::: "memory");
    }

    int a_row = wm * 64 + (lane & 15);
    int a_cb  = lane >> 4;
    int b_row = wn * 64 + (lane & 7) + (lane >> 4) * 8;
    int b_cb  = (lane >> 3) & 1;

    for (int kt = 0; kt < nk; kt += 2) {
        if (kt + 2 < nk) {
            asm volatile("cp.async.wait_group 2;" ::: "memory");
        } else {
            asm volatile("cp.async.wait_group 0;" ::: "memory");
        }
        __syncthreads();

        if (kt + 2 < nk) {
            fill_stage(s0 + ((kt + 2) & 3) * STAGE_B, kt + 2, m0, n0, K, Ahi, Alo, Bh, tid);
            asm volatile("cp.async.commit_group;" ::: "memory");
        }
        if (kt + 3 < nk) {
            fill_stage(s0 + ((kt + 3) & 3) * STAGE_B, kt + 3, m0, n0, K, Ahi, Alo, Bh, tid);
            asm volatile("cp.async.commit_group;" ::: "memory");
        }

        #pragma unroll
        for (int half = 0; half < 2; half++) {
            uint32_t sb = s0 + ((kt + half) & 3) * STAGE_B;
            uint32_t sbB = sb + 2 * TILE_B;

            uint32_t a[2][4][4];
            uint32_t bfr[2][4];
            #pragma unroll
            for (int hl = 0; hl < 2; hl++)
                #pragma unroll
                for (int mt = 0; mt < 4; mt++)
                    ldm_x4(a[hl][mt], sb + hl * TILE_B + swz(a_row + mt * 16, a_cb));
            ldm_x4(bfr[0], sbB + swz(b_row, b_cb));

            #pragma unroll
            for (int idx = 0; idx < 8; idx++) {
                int buf = idx & 1;
                if (idx < 7) {
                    int nks = (idx + 1) >> 2, nnp = (idx + 1) & 3;
                    ldm_x4(bfr[buf ^ 1], sbB + swz(b_row + nnp * 16, nks * 2 + b_cb));
                }
                int np = idx & 3;
                uint32_t* bh = bfr[buf];
                #pragma unroll
                for (int mt = 0; mt < 4; mt++)
                    #pragma unroll
                    for (int nt = 0; nt < 2; nt++)
                        mma_f16(acc[mt][np * 2 + nt], a[0][mt], &bh[nt * 2]);
                #pragma unroll
                for (int mt = 0; mt < 4; mt++)
                    #pragma unroll
                    for (int nt = 0; nt < 2; nt++)
                        mma_f16(acc[mt][np * 2 + nt], a[1][mt], &bh[nt * 2]);
                if (idx == 3) {
                    #pragma unroll
                    for (int hl = 0; hl < 2; hl++)
                        #pragma unroll
                        for (int mt = 0; mt < 4; mt++)
                            ldm_x4(a[hl][mt], sb + hl * TILE_B + swz(a_row + mt * 16, 2 + a_cb));
                }
            }
        }
    }

    if (!FUSED) {
        int row0 = m0 + wm * 64 + (lane >> 2);
        int col0 = n0 + wn * 64 + (lane & 3) * 2;
        #pragma unroll
        for (int mt = 0; mt < 4; mt++)
            #pragma unroll
            for (int nt = 0; nt < 8; nt++) {
                float* d = acc[mt][nt];
                long r = row0 + mt * 16;
                long c = col0 + nt * 8;
                *(float2*)(C + r * N + c)       = make_float2(d[0], d[1]);
                *(float2*)(C + (r + 8) * N + c) = make_float2(d[2], d[3]);
            }
        return;
    }

    // ===== fused epilogue: RMSNorm + RoPE + scatter (one slot per n-tile) =====
    __syncthreads();                 // all warps done with stage smem
    float* fsm = (float*)smraw;      // 128 rows x pitch 129 floats
    {
        int r0l = wm * 64 + (lane >> 2);
        int c0l = wn * 64 + (lane & 3) * 2;
        #pragma unroll
        for (int mt = 0; mt < 4; mt++)
            #pragma unroll
            for (int nt = 0; nt < 8; nt++) {
                float* d = acc[mt][nt];
                int rr = r0l + mt * 16;
                int cc = c0l + nt * 8;
                fsm[rr * 129 + cc]           = d[0];
                fsm[rr * 129 + cc + 1]       = d[1];
                fsm[(rr + 8) * 129 + cc]     = d[2];
                fsm[(rr + 8) * 129 + cc + 1] = d[3];
            }
    }
    __syncthreads();

    int slot = n0 >> 7;              // 0..47
    int b    = m0 >> 10;             // tile fully inside one batch (QN % 128 == 0)
    int pos_base = start[b];

    float wv0 = 0.f, wv1 = 0.f, wv2 = 0.f, wv3 = 0.f;
    if (slot < 40) {
        const float* wgt = (slot < 32) ? qw : kw;
        wv0 = wgt[lane]; wv1 = wgt[lane + 32]; wv2 = wgt[lane + 64]; wv3 = wgt[lane + 96];
    }

    for (int rr = 0; rr < 32; rr++) {
        int r = wid * 32 + rr;
        int m = m0 + r;
        int q = m & (QN - 1);
        int pos = pos_base + q;
        float x0 = fsm[r * 129 + lane];
        float x1 = fsm[r * 129 + lane + 32];
        float x2 = fsm[r * 129 + lane + 64];
        float x3 = fsm[r * 129 + lane + 96];

        if (slot >= 40) {            // V: raw scatter fp32 + fp16
            int hh = slot - 40;
            long ci = (((long)b * HKV + hh) * MAXC + pos) * DD;
            out_v[ci + lane]      = x0;
            out_v[ci + lane + 32] = x1;
            out_v[ci + lane + 64] = x2;
            out_v[ci + lane + 96] = x3;
            long vi = (((long)b * HKV + hh) * KLEN + pos) * DD;
            gVc_h[vi + lane]      = __float2half_rn(x0);
            gVc_h[vi + lane + 32] = __float2half_rn(x1);
            gVc_h[vi + lane + 64] = __float2half_rn(x2);
            gVc_h[vi + lane + 96] = __float2half_rn(x3);
            continue;
        }

        float ss = x0 * x0 + x1 * x1 + x2 * x2 + x3 * x3;
        #pragma unroll
        for (int mm = 16; mm; mm >>= 1) ss += __shfl_xor_sync(0xffffffffu, ss, mm);
        float scl = rsqrtf(ss * (1.f / DD) + 1e-6f);
        float n0v = x0 * scl * wv0;
        float n1v = x1 * scl * wv1;
        float n2v = x2 * scl * wv2;
        float n3v = x3 * scl * wv3;

        const float* rp = rope + (long)pos * DD;
        float c0 = rp[lane], c1 = rp[lane + 32];
        float sn0 = rp[lane + 64], sn1 = rp[lane + 96];
        float o0 = n0v * c0 - n2v * sn0;
        float o1 = n1v * c1 - n3v * sn1;
        float o2 = n2v * c0 + n0v * sn0;
        float o3 = n3v * c1 + n1v * sn1;

        if (slot < 32) {             // Q: scaled fp16 hi/lo (log2 domain)
            const float k = SCALE * LOG2E;
            o0 *= k; o1 *= k; o2 *= k; o3 *= k;
            long qi = (((long)b * HH + slot) * QN + q) * DD;
            __half h0 = __float2half_rn(o0), h1 = __float2half_rn(o1);
            __half h2 = __float2half_rn(o2), h3 = __float2half_rn(o3);
            gQ_hi[qi + lane]      = h0;
            gQ_hi[qi + lane + 32] = h1;
            gQ_hi[qi + lane + 64] = h2;
            gQ_hi[qi + lane + 96] = h3;
            gQ_lo[qi + lane]      = __float2half_rn(o0 - __half2float(h0));
            gQ_lo[qi + lane + 32] = __float2half_rn(o1 - __half2float(h1));
            gQ_lo[qi + lane + 64] = __float2half_rn(o2 - __half2float(h2));
            gQ_lo[qi + lane + 96] = __float2half_rn(o3 - __half2float(h3));
        } else {                     // K: fp32 scatter + fp16
            int hh = slot - 32;
            long ci = (((long)b * HKV + hh) * MAXC + pos) * DD;
            out_k[ci + lane]      = o0;
            out_k[ci + lane + 32] = o1;
            out_k[ci + lane + 64] = o2;
            out_k[ci + lane + 96] = o3;
            long ki = (((long)b * HKV + hh) * KLEN + pos) * DD;
            gKc_h[ki + lane]      = __float2half_rn(o0);
            gKc_h[ki + lane + 32] = __float2half_rn(o1);
            gKc_h[ki + lane + 64] = __float2half_rn(o2);
            gKc_h[ki + lane + 96] = __float2half_rn(o3);
        }
    }
}

// ================= flash attention =================
#define APITCHB 272
#define AQ 64
#define ATILE (AQ * APITCHB)
#define ATTN_SMEM (6 * ATILE)

__device__ __forceinline__ void load_tile_h(uint32_t dst,
    const __half* src, long rowbase, int tid)
{
    #pragma unroll
    for (int i = 0; i < 8; i++) {
        int idx = tid + i * 128;
        int row = idx >> 4, ch = idx & 15;
        cp16(dst + row * APITCHB + ch * 16, src + rowbase + (long)row * DD + (ch << 3));
    }
}

__global__ void __launch_bounds__(128, 2) attn_mma()
{
    extern __shared__ char smraw[];
    uint32_t T0 = smem_u32(smraw);
    int tid = threadIdx.x, lane = tid & 31, w = tid >> 5;
    int qt = gridDim.x - 1 - blockIdx.x;
    int h = blockIdx.y, b = blockIdx.z;
    int kvh = h >> 2;
    int q0 = qt * 64;

    long qbase  = ((long)(b * HH + h) * QN + q0) * DD;
    long kvbase = (long)(b * HKV + kvh) * KLEN * DD;

    const int a_row  = w * 16 + (lane & 15);
    const int a_kb   = (lane >> 4) * 16;
    const int b_row  = (lane & 7) + (lane >> 4) * 8;
    const int b_kb   = ((lane >> 3) & 1) * 16;
    const int v_row  = lane & 15;
    const int v_col  = (lane >> 4) * 8;

    load_tile_h(T0 + 4 * ATILE, gQ_hi, qbase, tid);
    load_tile_h(T0 + 5 * ATILE, gQ_lo, qbase, tid);
    load_tile_h(T0,             gKc_h, kvbase, tid);
    load_tile_h(T0 + ATILE,     gVc_h, kvbase, tid);
    asm volatile("cp.async.commit_group;" ::: "memory");
    load_tile_h(T0 + 2 * ATILE, gKc_h, kvbase + 64 * DD, tid);
    load_tile_h(T0 + 3 * ATILE, gVc_h, kvbase + 64 * DD, tid);
    asm volatile("cp.async.commit_group;" ::: "memory");

    asm volatile("cp.async.wait_group 1;" ::: "memory");
    __syncthreads();

    uint32_t qfr[8][2][4];
    #pragma unroll
    for (int ks = 0; ks < 8; ks++) {
        uint32_t qa = T0 + 4 * ATILE + a_row * APITCHB + ks * 32 + a_kb;
        ldm_x4(qfr[ks][0], qa);
        ldm_x4(qfr[ks][1], qa + ATILE);
    }

    const int nc = 17 + qt;

    float O[16][4];
    #pragma unroll
    for (int i = 0; i < 16; i++)
        #pragma unroll
        for (int j = 0; j < 4; j++) O[i][j] = 0.f;
    float m0 = -1e30f, m1 = -1e30f, l0 = 0.f, l1 = 0.f;

    for (int c = 0; c < nc; c++) {
        int st = c % 3;
        uint32_t sK = T0 + 2 * st * ATILE;
        uint32_t sV = sK + ATILE;

        asm volatile("cp.async.wait_group 1;" ::: "memory");
        __syncthreads();

        if (c + 2 < nc) {
            int rs = (c + 2) % 3;
            long nb = kvbase + (long)(c + 2) * 64 * DD;
            load_tile_h(T0 + 2 * rs * ATILE,       gKc_h, nb, tid);
            load_tile_h(T0 + (2 * rs + 1) * ATILE, gVc_h, nb, tid);
        }
        asm volatile("cp.async.commit_group;" ::: "memory");

        float S[8][4];
        #pragma unroll
        for (int j = 0; j < 8; j++)
            #pragma unroll
            for (int k = 0; k < 4; k++) S[j][k] = 0.f;

        #pragma unroll
        for (int ks = 0; ks < 8; ks++) {
            uint32_t kf[4][4];
            #pragma unroll
            for (int np = 0; np < 4; np++)
                ldm_x4(kf[np], sK + (np * 16 + b_row) * APITCHB + ks * 32 + b_kb);
            #pragma unroll
            for (int np = 0; np < 4; np++)
                #pragma unroll
                for (int nt = 0; nt < 2; nt++)
                    mma_f16(S[np * 2 + nt], qfr[ks][0], &kf[np][nt * 2]);
            #pragma unroll
            for (int np = 0; np < 4; np++)
                #pragma unroll
                for (int nt = 0; nt < 2; nt++)
                    mma_f16(S[np * 2 + nt], qfr[ks][1], &kf[np][nt * 2]);
        }

        if (c == nc - 1) {
            int klim0 = PAST + q0 + w * 16 + (lane >> 2);
            int klim1 = klim0 + 8;
            int kb = c * 64;
            #pragma unroll
            for (int j = 0; j < 8; j++) {
                int col = kb + j * 8 + (lane & 3) * 2;
                if (col > klim0)     S[j][0] = -1e30f;
                if (col + 1 > klim0) S[j][1] = -1e30f;
                if (col > klim1)     S[j][2] = -1e30f;
                if (col + 1 > klim1) S[j][3] = -1e30f;
            }
        }

        float mx0 = -1e30f, mx1 = -1e30f;
        #pragma unroll
        for (int j = 0; j < 8; j++) {
            mx0 = fmaxf(mx0, fmaxf(S[j][0], S[j][1]));
            mx1 = fmaxf(mx1, fmaxf(S[j][2], S[j][3]));
        }
        mx0 = fmaxf(mx0, __shfl_xor_sync(0xffffffffu, mx0, 1));
        mx0 = fmaxf(mx0, __shfl_xor_sync(0xffffffffu, mx0, 2));
        mx1 = fmaxf(mx1, __shfl_xor_sync(0xffffffffu, mx1, 1));
        mx1 = fmaxf(mx1, __shfl_xor_sync(0xffffffffu, mx1, 2));
        float mn0 = fmaxf(m0, mx0), mn1 = fmaxf(m1, mx1);
        float al0 = ex2(m0 - mn0), al1 = ex2(m1 - mn1);
        float r0 = 0.f, r1 = 0.f;
        #pragma unroll
        for (int j = 0; j < 8; j++) {
            S[j][0] = ex2(S[j][0] - mn0);
            S[j][1] = ex2(S[j][1] - mn0);
            S[j][2] = ex2(S[j][2] - mn1);
            S[j][3] = ex2(S[j][3] - mn1);
            r0 += S[j][0] + S[j][1];
            r1 += S[j][2] + S[j][3];
        }
        r0 += __shfl_xor_sync(0xffffffffu, r0, 1);
        r0 += __shfl_xor_sync(0xffffffffu, r0, 2);
        r1 += __shfl_xor_sync(0xffffffffu, r1, 1);
        r1 += __shfl_xor_sync(0xffffffffu, r1, 2);
        l0 = l0 * al0 + r0;
        l1 = l1 * al1 + r1;
        m0 = mn0; m1 = mn1;
        #pragma unroll
        for (int i = 0; i < 16; i++) {
            O[i][0] *= al0; O[i][1] *= al0;
            O[i][2] *= al1; O[i][3] *= al1;
        }

        uint32_t pa_h[4][4], pa_l[4][4];
        #pragma unroll
        for (int kt = 0; kt < 4; kt++) {
            int j0 = 2 * kt, j1 = 2 * kt + 1;
            float v00 = S[j0][0], v01 = S[j0][1], v02 = S[j0][2], v03 = S[j0][3];
            float v10 = S[j1][0], v11 = S[j1][1], v12 = S[j1][2], v13 = S[j1][3];
            pa_h[kt][0] = pack_h2(v00, v01);
            pa_h[kt][1] = pack_h2(v02, v03);
            pa_h[kt][2] = pack_h2(v10, v11);
            pa_h[kt][3] = pack_h2(v12, v13);
            __half2* hp;
            hp = (__half2*)&pa_h[kt][0];
            pa_l[kt][0] = pack_h2(v00 - __half2float(hp->x), v01 - __half2float(hp->y));
            hp = (__half2*)&pa_h[kt][1];
            pa_l[kt][1] = pack_h2(v02 - __half2float(hp->x), v03 - __half2float(hp->y));
            hp = (__half2*)&pa_h[kt][2];
            pa_l[kt][2] = pack_h2(v10 - __half2float(hp->x), v11 - __half2float(hp->y));
            hp = (__half2*)&pa_h[kt][3];
            pa_l[kt][3] = pack_h2(v12 - __half2float(hp->x), v13 - __half2float(hp->y));
        }

        #pragma unroll
        for (int kt = 0; kt < 4; kt++) {
            #pragma unroll
            for (int npp = 0; npp < 4; npp++) {
                int np0 = npp * 2, np1 = npp * 2 + 1;
                uint32_t vf0[4], vf1[4];
                ldm_x4t(vf0, sV + (kt * 16 + v_row) * APITCHB + (np0 * 16 + v_col) * 2);
                ldm_x4t(vf1, sV + (kt * 16 + v_row) * APITCHB + (np1 * 16 + v_col) * 2);
                mma_f16(O[np0 * 2 + 0], pa_h[kt], &vf0[0]);
                mma_f16(O[np0 * 2 + 1], pa_h[kt], &vf0[2]);
                mma_f16(O[np1 * 2 + 0], pa_h[kt], &vf1[0]);
                mma_f16(O[np1 * 2 + 1], pa_h[kt], &vf1[2]);
                mma_f16(O[np0 * 2 + 0], pa_l[kt], &vf0[0]);
                mma_f16(O[np0 * 2 + 1], pa_l[kt], &vf0[2]);
                mma_f16(O[np1 * 2 + 0], pa_l[kt], &vf1[0]);
                mma_f16(O[np1 * 2 + 1], pa_l[kt], &vf1[2]);
            }
        }
    }

    float inv0 = 1.f / l0, inv1 = 1.f / l1;
    int row0 = q0 + w * 16 + (lane >> 2);
    float* ob = g_attnO + ((long)(b * HH + h) * QN) * DD;
    #pragma unroll
    for (int np = 0; np < 16; np++) {
        int col = np * 8 + (lane & 3) * 2;
        *(float2*)(ob + (long)row0 * DD + col)       = make_float2(O[np][0] * inv0, O[np][1] * inv0);
        *(float2*)(ob + (long)(row0 + 8) * DD + col) = make_float2(O[np][2] * inv1, O[np][3] * inv1);
    }
}

// ---------------- group sum + fp16 hi/lo ----------------
__global__ void group_sum_kernel()
{
    long i = (long)blockIdx.x * 256 + threadIdx.x;
    if (i >= (long)BB * QN * HKV * DD) return;
    int d = (int)(i & (DD - 1));
    long t = i >> 7;
    int kvh = (int)(t & (HKV - 1));
    t >>= 3;
    int q = (int)(t % QN);
    int b = (int)(t / QN);
    float sum = 0.f;
    #pragma unroll
    for (int g = 0; g < GROUPS; g++)
        sum += g_attnO[(((long)b * HH + kvh * GROUPS + g) * QN + q) * DD + d];
    __half h = __float2half_rn(sum);
    gXo_hi[i] = h;
    gXo_lo[i] = __float2half_rn(sum - __half2float(h));
}

// ---------------- launch ----------------
static __half* sym_addr_h(const void* sym) {
    void* p = nullptr;
    cudaGetSymbolAddress(&p, sym);
    return (__half*)p;
}

extern "C" void kernel_launch(void* const* d_in, const int* in_sizes, int n_in,
                              void* d_out, int out_size)
{
    const float* hidden = (const float*)d_in[0];
    const float* kcache = (const float*)d_in[1];
    const float* vcache = (const float*)d_in[2];
    const float* rope   = (const float*)d_in[3];
    const int*   start  = (const int*)  d_in[5];
    const float* w_qkv  = (const float*)d_in[6];
    const float* w_o    = (const float*)d_in[7];
    const float* qw     = (const float*)d_in[8];
    const float* kw     = (const float*)d_in[9];

    float* out      = (float*)d_out;
    float* out_attn = out;
    float* out_k    = out + OUT_SZ1;
    float* out_v    = out + OUT_SZ1 + CACHE_SZ;

    __half* sA_hi = sym_addr_h(gA_hi);  __half* sA_lo = sym_addr_h(gA_lo);
    __half* sWq_h = sym_addr_h(gWq_h);  __half* sWo_h = sym_addr_h(gWo_h);
    __half* sXo_hi = sym_addr_h(gXo_hi); __half* sXo_lo = sym_addr_h(gXo_lo);

    cudaFuncSetAttribute(gemm_mma<true>,  cudaFuncAttributeMaxDynamicSharedMemorySize, GEMM_SMEM);
    cudaFuncSetAttribute(gemm_mma<false>, cudaFuncAttributeMaxDynamicSharedMemorySize, GEMM_SMEM);
    cudaFuncSetAttribute(attn_mma, cudaFuncAttributeMaxDynamicSharedMemorySize, ATTN_SMEM);

    // 1. fused prep: cache copy + PAST fp16 + A hi/lo
    prep_inputs<<<(CACHE_SZ + 255) / 256, 256>>>(hidden, kcache, vcache, out_k, out_v);

    // 2. weight conversions
    conv_T_h<<<dim3(NQKV / 32, HID / 32), dim3(32, 8)>>>(w_qkv, sWq_h, HID, NQKV);
    conv_T_h<<<dim3(HID / 32, (HKV*DD) / 32), dim3(32, 8)>>>(w_o, sWo_h, HKV*DD, HID);

    // 3. QKV projection with fused RMSNorm+RoPE+scatter epilogue
    gemm_mma<true><<<dim3(NQKV / 128, (BB*QN) / 128), 128, GEMM_SMEM>>>(
        sA_hi, sA_lo, sWq_h, nullptr, BB*QN, NQKV, HID,
        rope, start, qw, kw, out_k, out_v);

    // 4. flash attention
    attn_mma<<<dim3(QN / 64, HH, BB), 128, ATTN_SMEM>>>();

    // 5. group-sum + fp16 hi/lo
    group_sum_kernel<<<(BB*QN*HKV*DD + 255) / 256, 256>>>();

    // 6. output projection (plain epilogue)
    gemm_mma<false><<<dim3(HID / 128, (BB*QN) / 128), 128, GEMM_SMEM>>>(
        sXo_hi, sXo_lo, sWo_h, out_attn, BB*QN, HID, HKV*DD,
        nullptr, nullptr, nullptr, nullptr, nullptr, nullptr);
}

// round 16
// speedup vs baseline: 1.1341x; 1.0898x over previous
#include <cuda_runtime.h>
#include <cuda_fp16.h>
#include <cstdint>

// ---------------- problem constants ----------------
#define BB    2
#define QN    1024
#define PAST  1024
#define MAXC  4096
#define HH    32
#define HKV   8
#define DD    128
#define HID   4096
#define KLEN  (PAST + QN)
#define NQKV  ((HH + 2*HKV) * DD)
#define GROUPS (HH / HKV)
#define SCALE 0.08838834764831845f
#define LOG2E 1.4426950408889634f

#define OUT_SZ1 (BB*QN*HID)
#define CACHE_SZ (BB*HKV*MAXC*DD)

// ---------------- scratch ----------------
__device__ __align__(16) float g_attnO[BB*HH*QN*DD];

__device__ __align__(16) __half gA_hi [BB*QN*HID];
__device__ __align__(16) __half gA_lo [BB*QN*HID];
__device__ __align__(16) __half gWq_h [NQKV*HID];
__device__ __align__(16) __half gWo_h [HID*HKV*DD];
__device__ __align__(16) __half gXo_h [BB*QN*HKV*DD];

__device__ __align__(16) __half gQ_hi [BB*HH*QN*DD];
__device__ __align__(16) __half gQ_lo [BB*HH*QN*DD];
__device__ __align__(16) __half gKc_h [BB*HKV*KLEN*DD];
__device__ __align__(16) __half gVc_h [BB*HKV*KLEN*DD];

// ================= PTX helpers =================
__device__ __forceinline__ uint32_t smem_u32(const void* p) {
    uint32_t a;
    asm("{ .reg .u64 t; cvta.to.shared.u64 t, %1; cvt.u32.u64 %0, t; }" : "=r"(a) : "l"(p));
    return a;
}
__device__ __forceinline__ void ldm_x4(uint32_t* r, uint32_t addr) {
    asm volatile("ldmatrix.sync.aligned.m8n8.x4.shared.b16 {%0,%1,%2,%3}, [%4];"
                 : "=r"(r[0]), "=r"(r[1]), "=r"(r[2]), "=r"(r[3]) : "r"(addr));
}
__device__ __forceinline__ void ldm_x4t(uint32_t* r, uint32_t addr) {
    asm volatile("ldmatrix.sync.aligned.m8n8.x4.trans.shared.b16 {%0,%1,%2,%3}, [%4];"
                 : "=r"(r[0]), "=r"(r[1]), "=r"(r[2]), "=r"(r[3]) : "r"(addr));
}
__device__ __forceinline__ void mma_f16(float* d, const uint32_t* a, const uint32_t* b) {
    asm volatile(
        "mma.sync.aligned.m16n8k16.row.col.f32.f16.f16.f32 "
        "{%0,%1,%2,%3}, {%4,%5,%6,%7}, {%8,%9}, {%0,%1,%2,%3};"
        : "+f"(d[0]), "+f"(d[1]), "+f"(d[2]), "+f"(d[3])
        : "r"(a[0]), "r"(a[1]), "r"(a[2]), "r"(a[3]), "r"(b[0]), "r"(b[1]));
}
__device__ __forceinline__ void cp16(uint32_t dst, const void* src) {
    asm volatile("cp.async.cg.shared.global [%0], [%1], 16;" :: "r"(dst), "l"(src));
}
__device__ __forceinline__ uint32_t pack_h2(float x, float y) {
    __half2 h = __floats2half2_rn(x, y);
    return *(uint32_t*)&h;
}
__device__ __forceinline__ float ex2(float x) {
    float y;
    asm("ex2.approx.f32 %0, %1;" : "=f"(y) : "f"(x));
    return y;
}

// ================= fused input prep =================
__global__ void prep_inputs(const float* __restrict__ hidden,
                            const float* __restrict__ kc, const float* __restrict__ vc,
                            float* __restrict__ out_k, float* __restrict__ out_v) {
    long i = (long)blockIdx.x * 256 + threadIdx.x;
    if (i >= (long)CACHE_SZ) return;
    float kx = kc[i], vx = vc[i];
    out_k[i] = kx;
    out_v[i] = vx;
    int d = (int)(i & (DD - 1));
    long t = i >> 7;
    int pos = (int)(t & (MAXC - 1));
    if (pos < PAST) {
        long tt = t >> 12;
        long dst = (tt * KLEN + pos) * DD + d;
        gKc_h[dst] = __float2half_rn(kx);
        gVc_h[dst] = __float2half_rn(vx);
    }
    float x = hidden[i];
    __half h = __float2half_rn(x);
    gA_hi[i] = h;
    gA_lo[i] = __float2half_rn(x - __half2float(h));
}

__global__ void conv_T_h(const float* __restrict__ src, __half* __restrict__ hi,
                         int K, int N) {
    __shared__ float t[32][33];
    int bn = blockIdx.x * 32, bk = blockIdx.y * 32;
    int x = threadIdx.x, y = threadIdx.y;
    #pragma unroll
    for (int i = 0; i < 32; i += 8)
        t[y + i][x] = src[(long)(bk + y + i) * N + bn + x];
    __syncthreads();
    #pragma unroll
    for (int i = 0; i < 32; i += 8)
        hi[(long)(bn + y + i) * K + bk + x] = __float2half_rn(t[x][y + i]);
}

// ================= warp-MMA fp16 GEMM (TWOT: A hi/lo 2-term; else 1-term) =================
#define TILE_B  8192
#define NST     4
#define GEMM_SMEM2 (NST * 3 * TILE_B)      // 98304 (QKV, also holds fused epilogue 66 KB)
#define GEMM_SMEM1 (NST * 2 * TILE_B)      // 65536 (O-proj)

__device__ __forceinline__ uint32_t swz(int row, int ch) {
    return (uint32_t)(row * 64 + ((ch ^ ((row >> 1) & 3)) << 4));
}

template<bool TWOT>
__device__ __forceinline__ void fill_stage(
    uint32_t sb, int kt, int m0, int n0, int K,
    const __half* Ahi, const __half* Alo, const __half* Bh, int tid)
{
    long k0 = (long)kt * 32;
    const int NT = TWOT ? 3 : 2;
    const __half* bases[3] = {Ahi, TWOT ? Alo : Bh, Bh};
    #pragma unroll
    for (int t = 0; t < NT; t++) {
        const __half* bp = bases[TWOT ? t : (t == 0 ? 0 : 2)];
        int r0 = (TWOT ? (t < 2) : (t < 1)) ? m0 : n0;
        #pragma unroll
        for (int i = 0; i < 4; i++) {
            int idx = tid + i * 128;
            int row = idx >> 2, ch = idx & 3;
            cp16(sb + t * TILE_B + swz(row, ch), bp + (long)(r0 + row) * K + k0 + ch * 8);
        }
    }
}

template<bool FUSED, bool TWOT>
__global__ void __launch_bounds__(128, 2) gemm_mma(
    const __half* __restrict__ Ahi, const __half* __restrict__ Alo,
    const __half* __restrict__ Bh,
    float* __restrict__ C, int M, int N, int K,
    const float* __restrict__ rope, const int* __restrict__ start,
    const float* __restrict__ qw, const float* __restrict__ kw,
    float* __restrict__ out_k, float* __restrict__ out_v)
{
    extern __shared__ char smraw[];
    const uint32_t SB = (TWOT ? 3 : 2) * TILE_B;
    uint32_t s0 = smem_u32(smraw);
    int tid = threadIdx.x, lane = tid & 31, wid = tid >> 5;
    int wm = wid & 1, wn = wid >> 1;
    int m0 = blockIdx.y * 128, n0 = blockIdx.x * 128;

    float acc[4][8][4];
    #pragma unroll
    for (int i = 0; i < 4; i++)
        #pragma unroll
        for (int j = 0; j < 8; j++)
            #pragma unroll
            for (int k = 0; k < 4; k++) acc[i][j][k] = 0.f;

    int nk = K >> 5;
    #pragma unroll
    for (int p = 0; p < 4; p++) {
        fill_stage<TWOT>(s0 + p * SB, p, m0, n0, K, Ahi, Alo, Bh, tid);
        asm volatile("cp.async.commit_group;" ::: "memory");
    }

    int a_row = wm * 64 + (lane & 15);
    int a_cb  = lane >> 4;
    int b_row = wn * 64 + (lane & 7) + (lane >> 4) * 8;
    int b_cb  = (lane >> 3) & 1;
    const uint32_t BOFF = (TWOT ? 2 : 1) * TILE_B;

    for (int kt = 0; kt < nk; kt += 2) {
        if (kt + 2 < nk) {
            asm volatile("cp.async.wait_group 2;" ::: "memory");
        } else {
            asm volatile("cp.async.wait_group 0;" ::: "memory");
        }
        __syncthreads();

        if (kt + 2 < nk) {
            fill_stage<TWOT>(s0 + ((kt + 2) & 3) * SB, kt + 2, m0, n0, K, Ahi, Alo, Bh, tid);
            asm volatile("cp.async.commit_group;" ::: "memory");
        }
        if (kt + 3 < nk) {
            fill_stage<TWOT>(s0 + ((kt + 3) & 3) * SB, kt + 3, m0, n0, K, Ahi, Alo, Bh, tid);
            asm volatile("cp.async.commit_group;" ::: "memory");
        }

        #pragma unroll
        for (int half = 0; half < 2; half++) {
            uint32_t sb = s0 + ((kt + half) & 3) * SB;
            uint32_t sbB = sb + BOFF;

            uint32_t a[2][4][4];
            uint32_t bfr[2][4];
            #pragma unroll
            for (int mt = 0; mt < 4; mt++) {
                ldm_x4(a[0][mt], sb + swz(a_row + mt * 16, a_cb));
                if (TWOT) ldm_x4(a[1][mt], sb + TILE_B + swz(a_row + mt * 16, a_cb));
            }
            ldm_x4(bfr[0], sbB + swz(b_row, b_cb));

            #pragma unroll
            for (int idx = 0; idx < 8; idx++) {
                int buf = idx & 1;
                if (idx < 7) {
                    int nks = (idx + 1) >> 2, nnp = (idx + 1) & 3;
                    ldm_x4(bfr[buf ^ 1], sbB + swz(b_row + nnp * 16, nks * 2 + b_cb));
                }
                int np = idx & 3;
                uint32_t* bh = bfr[buf];
                #pragma unroll
                for (int mt = 0; mt < 4; mt++)
                    #pragma unroll
                    for (int nt = 0; nt < 2; nt++)
                        mma_f16(acc[mt][np * 2 + nt], a[0][mt], &bh[nt * 2]);
                if (TWOT) {
                    #pragma unroll
                    for (int mt = 0; mt < 4; mt++)
                        #pragma unroll
                        for (int nt = 0; nt < 2; nt++)
                            mma_f16(acc[mt][np * 2 + nt], a[1][mt], &bh[nt * 2]);
                }
                if (idx == 3) {
                    #pragma unroll
                    for (int mt = 0; mt < 4; mt++) {
                        ldm_x4(a[0][mt], sb + swz(a_row + mt * 16, 2 + a_cb));
                        if (TWOT) ldm_x4(a[1][mt], sb + TILE_B + swz(a_row + mt * 16, 2 + a_cb));
                    }
                }
            }
        }
    }

    if (!FUSED) {
        int row0 = m0 + wm * 64 + (lane >> 2);
        int col0 = n0 + wn * 64 + (lane & 3) * 2;
        #pragma unroll
        for (int mt = 0; mt < 4; mt++)
            #pragma unroll
            for (int nt = 0; nt < 8; nt++) {
                float* d = acc[mt][nt];
                long r = row0 + mt * 16;
                long c = col0 + nt * 8;
                *(float2*)(C + r * N + c)       = make_float2(d[0], d[1]);
                *(float2*)(C + (r + 8) * N + c) = make_float2(d[2], d[3]);
            }
        return;
    }

    // ===== fused epilogue: RMSNorm + RoPE + scatter (one slot per n-tile) =====
    __syncthreads();
    float* fsm = (float*)smraw;      // 128 x 129 floats
    {
        int r0l = wm * 64 + (lane >> 2);
        int c0l = wn * 64 + (lane & 3) * 2;
        #pragma unroll
        for (int mt = 0; mt < 4; mt++)
            #pragma unroll
            for (int nt = 0; nt < 8; nt++) {
                float* d = acc[mt][nt];
                int rr = r0l + mt * 16;
                int cc = c0l + nt * 8;
                fsm[rr * 129 + cc]           = d[0];
                fsm[rr * 129 + cc + 1]       = d[1];
                fsm[(rr + 8) * 129 + cc]     = d[2];
                fsm[(rr + 8) * 129 + cc + 1] = d[3];
            }
    }
    __syncthreads();

    int slot = n0 >> 7;
    int b    = m0 >> 10;
    int pos_base = start[b];

    float wv0 = 0.f, wv1 = 0.f, wv2 = 0.f, wv3 = 0.f;
    if (slot < 40) {
        const float* wgt = (slot < 32) ? qw : kw;
        wv0 = wgt[lane]; wv1 = wgt[lane + 32]; wv2 = wgt[lane + 64]; wv3 = wgt[lane + 96];
    }

    for (int rr = 0; rr < 32; rr++) {
        int r = wid * 32 + rr;
        int m = m0 + r;
        int q = m & (QN - 1);
        int pos = pos_base + q;
        float x0 = fsm[r * 129 + lane];
        float x1 = fsm[r * 129 + lane + 32];
        float x2 = fsm[r * 129 + lane + 64];
        float x3 = fsm[r * 129 + lane + 96];

        if (slot >= 40) {
            int hh = slot - 40;
            long ci = (((long)b * HKV + hh) * MAXC + pos) * DD;
            out_v[ci + lane]      = x0;
            out_v[ci + lane + 32] = x1;
            out_v[ci + lane + 64] = x2;
            out_v[ci + lane + 96] = x3;
            long vi = (((long)b * HKV + hh) * KLEN + pos) * DD;
            gVc_h[vi + lane]      = __float2half_rn(x0);
            gVc_h[vi + lane + 32] = __float2half_rn(x1);
            gVc_h[vi + lane + 64] = __float2half_rn(x2);
            gVc_h[vi + lane + 96] = __float2half_rn(x3);
            continue;
        }

        float ss = x0 * x0 + x1 * x1 + x2 * x2 + x3 * x3;
        #pragma unroll
        for (int mm = 16; mm; mm >>= 1) ss += __shfl_xor_sync(0xffffffffu, ss, mm);
        float scl = rsqrtf(ss * (1.f / DD) + 1e-6f);
        float n0v = x0 * scl * wv0;
        float n1v = x1 * scl * wv1;
        float n2v = x2 * scl * wv2;
        float n3v = x3 * scl * wv3;

        const float* rp = rope + (long)pos * DD;
        float c0 = rp[lane], c1 = rp[lane + 32];
        float sn0 = rp[lane + 64], sn1 = rp[lane + 96];
        float o0 = n0v * c0 - n2v * sn0;
        float o1 = n1v * c1 - n3v * sn1;
        float o2 = n2v * c0 + n0v * sn0;
        float o3 = n3v * c1 + n1v * sn1;

        if (slot < 32) {
            const float k = SCALE * LOG2E;
            o0 *= k; o1 *= k; o2 *= k; o3 *= k;
            long qi = (((long)b * HH + slot) * QN + q) * DD;
            __half h0 = __float2half_rn(o0), h1 = __float2half_rn(o1);
            __half h2 = __float2half_rn(o2), h3 = __float2half_rn(o3);
            gQ_hi[qi + lane]      = h0;
            gQ_hi[qi + lane + 32] = h1;
            gQ_hi[qi + lane + 64] = h2;
            gQ_hi[qi + lane + 96] = h3;
            gQ_lo[qi + lane]      = __float2half_rn(o0 - __half2float(h0));
            gQ_lo[qi + lane + 32] = __float2half_rn(o1 - __half2float(h1));
            gQ_lo[qi + lane + 64] = __float2half_rn(o2 - __half2float(h2));
            gQ_lo[qi + lane + 96] = __float2half_rn(o3 - __half2float(h3));
        } else {
            int hh = slot - 32;
            long ci = (((long)b * HKV + hh) * MAXC + pos) * DD;
            out_k[ci + lane]      = o0;
            out_k[ci + lane + 32] = o1;
            out_k[ci + lane + 64] = o2;
            out_k[ci + lane + 96] = o3;
            long ki = (((long)b * HKV + hh) * KLEN + pos) * DD;
            gKc_h[ki + lane]      = __float2half_rn(o0);
            gKc_h[ki + lane + 32] = __float2half_rn(o1);
            gKc_h[ki + lane + 64] = __float2half_rn(o2);
            gKc_h[ki + lane + 96] = __float2half_rn(o3);
        }
    }
}

// ================= flash attention (Q 2-term; P 1-term) =================
#define APITCHB 272
#define AQ 64
#define ATILE (AQ * APITCHB)
#define ATTN_SMEM (6 * ATILE)

__device__ __forceinline__ void load_tile_h(uint32_t dst,
    const __half* src, long rowbase, int tid)
{
    #pragma unroll
    for (int i = 0; i < 8; i++) {
        int idx = tid + i * 128;
        int row = idx >> 4, ch = idx & 15;
        cp16(dst + row * APITCHB + ch * 16, src + rowbase + (long)row * DD + (ch << 3));
    }
}

__global__ void __launch_bounds__(128, 2) attn_mma()
{
    extern __shared__ char smraw[];
    uint32_t T0 = smem_u32(smraw);
    int tid = threadIdx.x, lane = tid & 31, w = tid >> 5;
    int qt = gridDim.x - 1 - blockIdx.x;
    int h = blockIdx.y, b = blockIdx.z;
    int kvh = h >> 2;
    int q0 = qt * 64;

    long qbase  = ((long)(b * HH + h) * QN + q0) * DD;
    long kvbase = (long)(b * HKV + kvh) * KLEN * DD;

    const int a_row  = w * 16 + (lane & 15);
    const int a_kb   = (lane >> 4) * 16;
    const int b_row  = (lane & 7) + (lane >> 4) * 8;
    const int b_kb   = ((lane >> 3) & 1) * 16;
    const int v_row  = lane & 15;
    const int v_col  = (lane >> 4) * 8;

    load_tile_h(T0 + 4 * ATILE, gQ_hi, qbase, tid);
    load_tile_h(T0 + 5 * ATILE, gQ_lo, qbase, tid);
    load_tile_h(T0,             gKc_h, kvbase, tid);
    load_tile_h(T0 + ATILE,     gVc_h, kvbase, tid);
    asm volatile("cp.async.commit_group;" ::: "memory");
    load_tile_h(T0 + 2 * ATILE, gKc_h, kvbase + 64 * DD, tid);
    load_tile_h(T0 + 3 * ATILE, gVc_h, kvbase + 64 * DD, tid);
    asm volatile("cp.async.commit_group;" ::: "memory");

    asm volatile("cp.async.wait_group 1;" ::: "memory");
    __syncthreads();

    uint32_t qfr[8][2][4];
    #pragma unroll
    for (int ks = 0; ks < 8; ks++) {
        uint32_t qa = T0 + 4 * ATILE + a_row * APITCHB + ks * 32 + a_kb;
        ldm_x4(qfr[ks][0], qa);
        ldm_x4(qfr[ks][1], qa + ATILE);
    }

    const int nc = 17 + qt;

    float O[16][4];
    #pragma unroll
    for (int i = 0; i < 16; i++)
        #pragma unroll
        for (int j = 0; j < 4; j++) O[i][j] = 0.f;
    float m0 = -1e30f, m1 = -1e30f, l0 = 0.f, l1 = 0.f;

    for (int c = 0; c < nc; c++) {
        int st = c % 3;
        uint32_t sK = T0 + 2 * st * ATILE;
        uint32_t sV = sK + ATILE;

        asm volatile("cp.async.wait_group 1;" ::: "memory");
        __syncthreads();

        if (c + 2 < nc) {
            int rs = (c + 2) % 3;
            long nb = kvbase + (long)(c + 2) * 64 * DD;
            load_tile_h(T0 + 2 * rs * ATILE,       gKc_h, nb, tid);
            load_tile_h(T0 + (2 * rs + 1) * ATILE, gVc_h, nb, tid);
        }
        asm volatile("cp.async.commit_group;" ::: "memory");

        float S[8][4];
        #pragma unroll
        for (int j = 0; j < 8; j++)
            #pragma unroll
            for (int k = 0; k < 4; k++) S[j][k] = 0.f;

        #pragma unroll
        for (int ks = 0; ks < 8; ks++) {
            uint32_t kf[4][4];
            #pragma unroll
            for (int np = 0; np < 4; np++)
                ldm_x4(kf[np], sK + (np * 16 + b_row) * APITCHB + ks * 32 + b_kb);
            #pragma unroll
            for (int np = 0; np < 4; np++)
                #pragma unroll
                for (int nt = 0; nt < 2; nt++)
                    mma_f16(S[np * 2 + nt], qfr[ks][0], &kf[np][nt * 2]);
            #pragma unroll
            for (int np = 0; np < 4; np++)
                #pragma unroll
                for (int nt = 0; nt < 2; nt++)
                    mma_f16(S[np * 2 + nt], qfr[ks][1], &kf[np][nt * 2]);
        }

        if (c == nc - 1) {
            int klim0 = PAST + q0 + w * 16 + (lane >> 2);
            int klim1 = klim0 + 8;
            int kb = c * 64;
            #pragma unroll
            for (int j = 0; j < 8; j++) {
                int col = kb + j * 8 + (lane & 3) * 2;
                if (col > klim0)     S[j][0] = -1e30f;
                if (col + 1 > klim0) S[j][1] = -1e30f;
                if (col > klim1)     S[j][2] = -1e30f;
                if (col + 1 > klim1) S[j][3] = -1e30f;
            }
        }

        float mx0 = -1e30f, mx1 = -1e30f;
        #pragma unroll
        for (int j = 0; j < 8; j++) {
            mx0 = fmaxf(mx0, fmaxf(S[j][0], S[j][1]));
            mx1 = fmaxf(mx1, fmaxf(S[j][2], S[j][3]));
        }
        mx0 = fmaxf(mx0, __shfl_xor_sync(0xffffffffu, mx0, 1));
        mx0 = fmaxf(mx0, __shfl_xor_sync(0xffffffffu, mx0, 2));
        mx1 = fmaxf(mx1, __shfl_xor_sync(0xffffffffu, mx1, 1));
        mx1 = fmaxf(mx1, __shfl_xor_sync(0xffffffffu, mx1, 2));
        float mn0 = fmaxf(m0, mx0), mn1 = fmaxf(m1, mx1);
        float al0 = ex2(m0 - mn0), al1 = ex2(m1 - mn1);
        float r0 = 0.f, r1 = 0.f;
        #pragma unroll
        for (int j = 0; j < 8; j++) {
            S[j][0] = ex2(S[j][0] - mn0);
            S[j][1] = ex2(S[j][1] - mn0);
            S[j][2] = ex2(S[j][2] - mn1);
            S[j][3] = ex2(S[j][3] - mn1);
            r0 += S[j][0] + S[j][1];
            r1 += S[j][2] + S[j][3];
        }
        r0 += __shfl_xor_sync(0xffffffffu, r0, 1);
        r0 += __shfl_xor_sync(0xffffffffu, r0, 2);
        r1 += __shfl_xor_sync(0xffffffffu, r1, 1);
        r1 += __shfl_xor_sync(0xffffffffu, r1, 2);
        l0 = l0 * al0 + r0;
        l1 = l1 * al1 + r1;
        m0 = mn0; m1 = mn1;
        #pragma unroll
        for (int i = 0; i < 16; i++) {
            O[i][0] *= al0; O[i][1] *= al0;
            O[i][2] *= al1; O[i][3] *= al1;
        }

        // ---- P -> fp16 A-frags (single term) ----
        uint32_t pa[4][4];
        #pragma unroll
        for (int kt = 0; kt < 4; kt++) {
            int j0 = 2 * kt, j1 = 2 * kt + 1;
            pa[kt][0] = pack_h2(S[j0][0], S[j0][1]);
            pa[kt][1] = pack_h2(S[j0][2], S[j0][3]);
            pa[kt][2] = pack_h2(S[j1][0], S[j1][1]);
            pa[kt][3] = pack_h2(S[j1][2], S[j1][3]);
        }

        // ---- O += P V (1-term) ----
        #pragma unroll
        for (int kt = 0; kt < 4; kt++) {
            #pragma unroll
            for (int npp = 0; npp < 4; npp++) {
                int np0 = npp * 2, np1 = npp * 2 + 1;
                uint32_t vf0[4], vf1[4];
                ldm_x4t(vf0, sV + (kt * 16 + v_row) * APITCHB + (np0 * 16 + v_col) * 2);
                ldm_x4t(vf1, sV + (kt * 16 + v_row) * APITCHB + (np1 * 16 + v_col) * 2);
                mma_f16(O[np0 * 2 + 0], pa[kt], &vf0[0]);
                mma_f16(O[np0 * 2 + 1], pa[kt], &vf0[2]);
                mma_f16(O[np1 * 2 + 0], pa[kt], &vf1[0]);
                mma_f16(O[np1 * 2 + 1], pa[kt], &vf1[2]);
            }
        }
    }

    float inv0 = 1.f / l0, inv1 = 1.f / l1;
    int row0 = q0 + w * 16 + (lane >> 2);
    float* ob = g_attnO + ((long)(b * HH + h) * QN) * DD;
    #pragma unroll
    for (int np = 0; np < 16; np++) {
        int col = np * 8 + (lane & 3) * 2;
        *(float2*)(ob + (long)row0 * DD + col)       = make_float2(O[np][0] * inv0, O[np][1] * inv0);
        *(float2*)(ob + (long)(row0 + 8) * DD + col) = make_float2(O[np][2] * inv1, O[np][3] * inv1);
    }
}

// ---------------- group sum -> single fp16 ----------------
__global__ void group_sum_kernel()
{
    long i = (long)blockIdx.x * 256 + threadIdx.x;
    if (i >= (long)BB * QN * HKV * DD) return;
    int d = (int)(i & (DD - 1));
    long t = i >> 7;
    int kvh = (int)(t & (HKV - 1));
    t >>= 3;
    int q = (int)(t % QN);
    int b = (int)(t / QN);
    float sum = 0.f;
    #pragma unroll
    for (int g = 0; g < GROUPS; g++)
        sum += g_attnO[(((long)b * HH + kvh * GROUPS + g) * QN + q) * DD + d];
    gXo_h[i] = __float2half_rn(sum);
}

// ---------------- launch ----------------
static __half* sym_addr_h(const void* sym) {
    void* p = nullptr;
    cudaGetSymbolAddress(&p, sym);
    return (__half*)p;
}

extern "C" void kernel_launch(void* const* d_in, const int* in_sizes, int n_in,
                              void* d_out, int out_size)
{
    const float* hidden = (const float*)d_in[0];
    const float* kcache = (const float*)d_in[1];
    const float* vcache = (const float*)d_in[2];
    const float* rope   = (const float*)d_in[3];
    const int*   start  = (const int*)  d_in[5];
    const float* w_qkv  = (const float*)d_in[6];
    const float* w_o    = (const float*)d_in[7];
    const float* qw     = (const float*)d_in[8];
    const float* kw     = (const float*)d_in[9];

    float* out      = (float*)d_out;
    float* out_attn = out;
    float* out_k    = out + OUT_SZ1;
    float* out_v    = out + OUT_SZ1 + CACHE_SZ;

    __half* sA_hi = sym_addr_h(gA_hi);  __half* sA_lo = sym_addr_h(gA_lo);
    __half* sWq_h = sym_addr_h(gWq_h);  __half* sWo_h = sym_addr_h(gWo_h);
    __half* sXo_h = sym_addr_h(gXo_h);

    cudaFuncSetAttribute((void*)gemm_mma<true, true>,   cudaFuncAttributeMaxDynamicSharedMemorySize, GEMM_SMEM2);
    cudaFuncSetAttribute((void*)gemm_mma<false, false>, cudaFuncAttributeMaxDynamicSharedMemorySize, GEMM_SMEM1);
    cudaFuncSetAttribute(attn_mma, cudaFuncAttributeMaxDynamicSharedMemorySize, ATTN_SMEM);

    // 1. fused prep
    prep_inputs<<<(CACHE_SZ + 255) / 256, 256>>>(hidden, kcache, vcache, out_k, out_v);

    // 2. weight conversions
    conv_T_h<<<dim3(NQKV / 32, HID / 32), dim3(32, 8)>>>(w_qkv, sWq_h, HID, NQKV);
    conv_T_h<<<dim3(HID / 32, (HKV*DD) / 32), dim3(32, 8)>>>(w_o, sWo_h, HKV*DD, HID);

    // 3. QKV projection (2-term) + fused RMSNorm/RoPE/scatter
    gemm_mma<true, true><<<dim3(NQKV / 128, (BB*QN) / 128), 128, GEMM_SMEM2>>>(
        sA_hi, sA_lo, sWq_h, nullptr, BB*QN, NQKV, HID,
        rope, start, qw, kw, out_k, out_v);

    // 4. flash attention (P single-term)
    attn_mma<<<dim3(QN / 64, HH, BB), 128, ATTN_SMEM>>>();

    // 5. group-sum -> fp16
    group_sum_kernel<<<(BB*QN*HKV*DD + 255) / 256, 256>>>();

    // 6. output projection (1-term)
    gemm_mma<false, false><<<dim3(HID / 128, (BB*QN) / 128), 128, GEMM_SMEM1>>>(
        sXo_h, nullptr, sWo_h, out_attn, BB*QN, HID, HKV*DD,
        nullptr, nullptr, nullptr, nullptr, nullptr, nullptr);
}